// round 10
// baseline (speedup 1.0000x reference)
#include <cuda_runtime.h>
#include <math.h>

#define BB 16
#define SS 96
#define TT 50
#define NR 1536          // B*S
#define NHID 1537        // rows of "hidden"
#define HID 128
#define G4 512           // 4*H
#define D2 256
#define G3 768           // 3*D2
#define GW 1536          // Gi(768) | Gh(768)
#define VSZ 32000

#define LROWS 7
#define LTHREADS 256
#define LBLOCKS 220      // ceil(1536/7)

typedef unsigned long long u64;

// ---------------- scratch (device globals; no allocations) ----------------
__device__ float g_Evoc[2][(size_t)VSZ * G4];  // emb_table @ Wih^T + b, per dir
__device__ float g_Wtp[2][128 * 512];          // packed: [k/4][j][k%4]
__device__ float g_hT[2][NR * HID];
__device__ float g_cT[2][NR * HID];
__device__ float g_hidA[NHID * D2];
__device__ float g_hidB[NHID * D2];
__device__ float g_G[NHID * GW];               // [Gi | Gh] per row
__device__ int   g_cnt[2][NR];
__device__ int4  g_tab[2][NR * SS];

__device__ __forceinline__ float sigf(float x) { return 1.f / (1.f + __expf(-x)); }
__device__ __forceinline__ float tanhfast(float x) {
    float t = __expf(2.f * x);
    return 1.f - 2.f / (t + 1.f);
}

// ---- packed f32x2 helpers (Blackwell sm_103a) ----
__device__ __forceinline__ void fma2(u64& d, u64 a, u64 b) {
    asm("fma.rn.f32x2 %0, %1, %2, %0;" : "+l"(d) : "l"(a), "l"(b));
}
__device__ __forceinline__ u64 packf2(float lo, float hi) {
    u64 r; asm("mov.b64 %0, {%1, %2};" : "=l"(r) : "f"(lo), "f"(hi)); return r;
}
__device__ __forceinline__ float2 unpackf2(u64 v) {
    float2 r; asm("mov.b64 {%0, %1}, %2;" : "=f"(r.x), "=f"(r.y) : "l"(v)); return r;
}

// ---------------------------------------------------------------------------
// Kernel 0b: pack Whh as Wtp[(k>>2)*2048 + j*4 + (k%4)] -> thread j fetches its
// 4-k quad with one coalesced LDG.128; quad = two natural f32x2 k-pairs.
// ---------------------------------------------------------------------------
__global__ void __launch_bounds__(256) pack_whh(
    const float* __restrict__ Whh_f, const float* __restrict__ Whh_b)
{
    int idx = blockIdx.x * blockDim.x + threadIdx.x;
    if (idx >= 512 * 128) return;
    int j = idx >> 7, k = idx & 127;
    int dst = (k >> 2) * 2048 + j * 4 + (k & 3);
    g_Wtp[0][dst] = Whh_f[idx];
    g_Wtp[1][dst] = Whh_b[idx];
}

// ---------------------------------------------------------------------------
// Kernel 1: Evoc[dir] = emb_table @ W^T + b.  M=32000, N=512, K=128.
// 128x128 tile, 8x8 micro via f32x2 pairs across j, BK=16, smem double buffer.
// ---------------------------------------------------------------------------
__global__ void __launch_bounds__(256) evoc_kernel(
    const float* __restrict__ emb,
    const float* __restrict__ Wf, const float* __restrict__ bf,
    const float* __restrict__ Wb, const float* __restrict__ bb)
{
    __shared__ __align__(16) float As[2][16][132];
    __shared__ __align__(16) float Bs[2][16][132];

    const int dir = blockIdx.z;
    const float* __restrict__ W = dir ? Wb : Wf;
    const float* __restrict__ bias = dir ? bb : bf;
    float* __restrict__ C = g_Evoc[dir];

    const int mb = blockIdx.x * 128;
    const int nb = blockIdx.y * 128;
    const int tid = threadIdx.x;
    const int tx = tid & 15, ty = tid >> 4;

    const int f0 = tid * 2, m0 = f0 >> 2, kq0 = (f0 & 3) * 4;
    const int f1 = tid * 2 + 1, m1 = f1 >> 2, kq1 = (f1 & 3) * 4;

    u64 accp[8][4];
    {
        float4 bv0 = *(const float4*)&bias[nb + tx * 4];
        float4 bv1 = *(const float4*)&bias[nb + 64 + tx * 4];
        u64 p0 = packf2(bv0.x, bv0.y), p1 = packf2(bv0.z, bv0.w);
        u64 p2 = packf2(bv1.x, bv1.y), p3 = packf2(bv1.z, bv1.w);
#pragma unroll
        for (int i = 0; i < 8; i++) {
            accp[i][0] = p0; accp[i][1] = p1; accp[i][2] = p2; accp[i][3] = p3;
        }
    }

    float4 ra0, ra1, rb0, rb1;
    ra0 = *(const float4*)&emb[(size_t)(mb + m0) * 128 + kq0];
    ra1 = *(const float4*)&emb[(size_t)(mb + m1) * 128 + kq1];
    rb0 = *(const float4*)&W[(size_t)(nb + m0) * 128 + kq0];
    rb1 = *(const float4*)&W[(size_t)(nb + m1) * 128 + kq1];
    As[0][kq0 + 0][m0] = ra0.x; As[0][kq0 + 1][m0] = ra0.y; As[0][kq0 + 2][m0] = ra0.z; As[0][kq0 + 3][m0] = ra0.w;
    As[0][kq1 + 0][m1] = ra1.x; As[0][kq1 + 1][m1] = ra1.y; As[0][kq1 + 2][m1] = ra1.z; As[0][kq1 + 3][m1] = ra1.w;
    Bs[0][kq0 + 0][m0] = rb0.x; Bs[0][kq0 + 1][m0] = rb0.y; Bs[0][kq0 + 2][m0] = rb0.z; Bs[0][kq0 + 3][m0] = rb0.w;
    Bs[0][kq1 + 0][m1] = rb1.x; Bs[0][kq1 + 1][m1] = rb1.y; Bs[0][kq1 + 2][m1] = rb1.z; Bs[0][kq1 + 3][m1] = rb1.w;
    __syncthreads();

    for (int c = 0; c < 8; c++) {
        const int cur = c & 1;
        if (c < 7) {
            int k0 = (c + 1) * 16;
            ra0 = *(const float4*)&emb[(size_t)(mb + m0) * 128 + k0 + kq0];
            ra1 = *(const float4*)&emb[(size_t)(mb + m1) * 128 + k0 + kq1];
            rb0 = *(const float4*)&W[(size_t)(nb + m0) * 128 + k0 + kq0];
            rb1 = *(const float4*)&W[(size_t)(nb + m1) * 128 + k0 + kq1];
        }
#pragma unroll
        for (int kk = 0; kk < 16; kk++) {
            float4 a0 = *(const float4*)&As[cur][kk][ty * 4];
            float4 a1 = *(const float4*)&As[cur][kk][64 + ty * 4];
            ulonglong2 bp0 = *(const ulonglong2*)&Bs[cur][kk][tx * 4];
            ulonglong2 bp1 = *(const ulonglong2*)&Bs[cur][kk][64 + tx * 4];
            float av[8] = {a0.x,a0.y,a0.z,a0.w,a1.x,a1.y,a1.z,a1.w};
#pragma unroll
            for (int i = 0; i < 8; i++) {
                u64 ad = packf2(av[i], av[i]);
                fma2(accp[i][0], ad, bp0.x);
                fma2(accp[i][1], ad, bp0.y);
                fma2(accp[i][2], ad, bp1.x);
                fma2(accp[i][3], ad, bp1.y);
            }
        }
        if (c < 7) {
            const int nxt = 1 - cur;
            As[nxt][kq0 + 0][m0] = ra0.x; As[nxt][kq0 + 1][m0] = ra0.y; As[nxt][kq0 + 2][m0] = ra0.z; As[nxt][kq0 + 3][m0] = ra0.w;
            As[nxt][kq1 + 0][m1] = ra1.x; As[nxt][kq1 + 1][m1] = ra1.y; As[nxt][kq1 + 2][m1] = ra1.z; As[nxt][kq1 + 3][m1] = ra1.w;
            Bs[nxt][kq0 + 0][m0] = rb0.x; Bs[nxt][kq0 + 1][m0] = rb0.y; Bs[nxt][kq0 + 2][m0] = rb0.z; Bs[nxt][kq0 + 3][m0] = rb0.w;
            Bs[nxt][kq1 + 0][m1] = rb1.x; Bs[nxt][kq1 + 1][m1] = rb1.y; Bs[nxt][kq1 + 2][m1] = rb1.z; Bs[nxt][kq1 + 3][m1] = rb1.w;
            __syncthreads();
        }
    }
#pragma unroll
    for (int i = 0; i < 8; i++) {
        int row = mb + (i < 4 ? ty * 4 + i : 64 + ty * 4 + (i - 4));
        size_t base = (size_t)row * G4 + nb;
        float2 q0 = unpackf2(accp[i][0]), q1 = unpackf2(accp[i][1]);
        float2 q2 = unpackf2(accp[i][2]), q3 = unpackf2(accp[i][3]);
        float4 o0 = {q0.x, q0.y, q1.x, q1.y};
        float4 o1 = {q2.x, q2.y, q3.x, q3.y};
        *(float4*)&C[base + tx * 4] = o0;
        *(float4*)&C[base + 64 + tx * 4] = o1;
    }
}

// ---------------------------------------------------------------------------
// Kernel 2: LSTM recurrence, f32x2 paired accumulators, 3 blocks/SM.
// LROWS=7 -> ~70 live regs under the 85-reg occupancy-3 cap; grid (220,2) =
// 440 blocks = 2.97/SM single uniform wave, 6 warps/SMSP for latency hiding.
// ---------------------------------------------------------------------------
__global__ void __launch_bounds__(LTHREADS, 3) lstm_kernel(const int* __restrict__ enc)
{
    const int dir = blockIdx.y;
    const int rowBase = blockIdx.x * LROWS;
    const float* __restrict__ Wp = g_Wtp[dir];
    const float* __restrict__ Ev = g_Evoc[dir];
    const int tid = threadIdx.x;
    const int j0 = tid, j1 = tid + 256;

    __shared__ __align__(16) float hs[LROWS][128];
    __shared__ __align__(16) float cs[LROWS][128];
    __shared__ float gs[LROWS][512];
    __shared__ int toks[LROWS * TT];

    for (int e = tid; e < LROWS * 128; e += LTHREADS) {
        ((float*)hs)[e] = 0.f; ((float*)cs)[e] = 0.f;
    }
    for (int x = tid; x < LROWS * TT; x += LTHREADS) {
        int r = x / TT, tt = x % TT;
        int row = rowBase + r; if (row > NR - 1) row = NR - 1;   // clamp pad rows
        toks[x] = enc[row * TT + tt];
    }
    __syncthreads();

    // prefetch step-0 x-gates into registers
    float xa0[LROWS], xa1[LROWS];
    {
        const int te0 = dir ? (TT - 1) : 0;
#pragma unroll
        for (int r = 0; r < LROWS; r++) {
            const float* ev = Ev + (size_t)toks[r * TT + te0] * G4;
            xa0[r] = __ldg(&ev[j0]);
            xa1[r] = __ldg(&ev[j1]);
        }
    }

#pragma unroll 1
    for (int t = 0; t < TT; t++) {
        u64 accA[LROWS], accB[LROWS];
#pragma unroll
        for (int r = 0; r < LROWS; r++) {
            accA[r] = packf2(xa0[r], 0.f);
            accB[r] = packf2(xa1[r], 0.f);
        }

        if (t + 1 < TT) {      // prefetch next step's gather behind this step's FMA
            const int tn = dir ? (TT - 2 - t) : (t + 1);
#pragma unroll
            for (int r = 0; r < LROWS; r++) {
                const float* ev = Ev + (size_t)toks[r * TT + tn] * G4;
                xa0[r] = __ldg(&ev[j0]);
                xa1[r] = __ldg(&ev[j1]);
            }
        }

        // h @ Whh^T: 32 chunks x 4 k; 2 LDG.128 + 7 LDS.128 + 28 FFMA2 / chunk
#pragma unroll 2
        for (int q = 0; q < 32; q++) {
            ulonglong2 wA = *(const ulonglong2*)&Wp[q * 2048 + j0 * 4];
            ulonglong2 wB = *(const ulonglong2*)&Wp[q * 2048 + j1 * 4];
#pragma unroll
            for (int r = 0; r < LROWS; r++) {
                ulonglong2 h2 = *(const ulonglong2*)&hs[r][q * 4];
                fma2(accA[r], wA.x, h2.x);
                fma2(accA[r], wA.y, h2.y);
                fma2(accB[r], wB.x, h2.x);
                fma2(accB[r], wB.y, h2.y);
            }
        }

#pragma unroll
        for (int r = 0; r < LROWS; r++) {
            float2 pA = unpackf2(accA[r]);
            float2 pB = unpackf2(accB[r]);
            gs[r][j0] = pA.x + pA.y;
            gs[r][j1] = pB.x + pB.y;
        }
        __syncthreads();
        for (int e = tid; e < LROWS * 128; e += LTHREADS) {
            int r = e >> 7, ch = e & 127;
            float gi = gs[r][ch],       gf = gs[r][128 + ch];
            float gg = gs[r][256 + ch], go = gs[r][384 + ch];
            float c = sigf(gf) * cs[r][ch] + sigf(gi) * tanhfast(gg);
            float h = sigf(go) * tanhfast(c);
            cs[r][ch] = c; hs[r][ch] = h;
        }
        __syncthreads();
    }

    for (int e = tid; e < LROWS * 128; e += LTHREADS) {
        int r = e >> 7, ch = e & 127;
        int n = rowBase + r;
        if (n < NR) {
            g_hT[dir][n * HID + ch] = hs[r][ch];
            g_cT[dir][n * HID + ch] = cs[r][ch];
        }
    }
}

// ---------------------------------------------------------------------------
// Kernel 3: hidden rows 1..1536 = [relu([cf|cb]@Wc^T+bc) | relu([hf|hb]@Whr^T+bhr)]
// ---------------------------------------------------------------------------
__global__ void __launch_bounds__(256) reduce_kernel(
    const float* __restrict__ Wc, const float* __restrict__ bc,
    const float* __restrict__ Whr, const float* __restrict__ bhr)
{
    const int nb = blockIdx.x * 8;
    const int tid = threadIdx.x;
    __shared__ __align__(16) float inA[8][256];
    __shared__ __align__(16) float inB[8][256];
    for (int x = tid; x < 8 * 256; x += 256) {
        int r = x >> 8, k = x & 255;
        int n = nb + r;
        inA[r][k] = (k < 128) ? g_cT[0][n * HID + k] : g_cT[1][n * HID + (k - 128)];
        inB[r][k] = (k < 128) ? g_hT[0][n * HID + k] : g_hT[1][n * HID + (k - 128)];
    }
    __syncthreads();

    const bool isC = tid < 128;
    const float* __restrict__ Wrow = isC ? (Wc + tid * 256) : (Whr + (tid - 128) * 256);
    const float bias = isC ? __ldg(&bc[tid]) : __ldg(&bhr[tid - 128]);
    const float (*IN)[256] = isC ? inA : inB;

    u64 accp[8];
#pragma unroll
    for (int r = 0; r < 8; r++) accp[r] = packf2(bias, 0.f);
#pragma unroll 4
    for (int k = 0; k < 256; k += 16) {
        ulonglong2 w0 = *(const ulonglong2*)&Wrow[k];
        ulonglong2 w1 = *(const ulonglong2*)&Wrow[k + 4];
        ulonglong2 w2 = *(const ulonglong2*)&Wrow[k + 8];
        ulonglong2 w3 = *(const ulonglong2*)&Wrow[k + 12];
#pragma unroll
        for (int r = 0; r < 8; r++) {
            ulonglong2 i0 = *(const ulonglong2*)&IN[r][k];
            ulonglong2 i1 = *(const ulonglong2*)&IN[r][k + 4];
            ulonglong2 i2 = *(const ulonglong2*)&IN[r][k + 8];
            ulonglong2 i3 = *(const ulonglong2*)&IN[r][k + 12];
            fma2(accp[r], w0.x, i0.x); fma2(accp[r], w0.y, i0.y);
            fma2(accp[r], w1.x, i1.x); fma2(accp[r], w1.y, i1.y);
            fma2(accp[r], w2.x, i2.x); fma2(accp[r], w2.y, i2.y);
            fma2(accp[r], w3.x, i3.x); fma2(accp[r], w3.y, i3.y);
        }
    }
#pragma unroll
    for (int r = 0; r < 8; r++) {
        float2 p = unpackf2(accp[r]);
        g_hidA[(nb + r + 1) * D2 + tid] = fmaxf(p.x + p.y, 0.f);
    }
    if (blockIdx.x == 0) g_hidA[tid] = 0.f;
}

// ---------------------------------------------------------------------------
// Kernel 3b: compacted active lists per (phase, output row). Deterministic.
// ---------------------------------------------------------------------------
__global__ void __launch_bounds__(256) build_tables(
    const int* __restrict__ sp, const int* __restrict__ sc,
    const float* __restrict__ mask)
{
    int g = blockIdx.x * blockDim.x + threadIdx.x;
    if (g >= 2 * NR) return;
    int phase = g >= NR;
    int o = g - phase * NR;
    int b = o / SS, q = o % SS;
    int n = 0;
    for (int u = 0; u < SS; u++) {
        int idx = phase ? ((b * SS + q) * SS + u) : ((b * SS + u) * SS + q);
        float mv = __ldg(&mask[idx]);
        if (mv != 0.f) {
            int par = __ldg(&sp[idx]);
            int chi = __ldg(&sc[idx]);
            int xr = phase ? par : chi;
            int hr = phase ? chi : par;
            g_tab[phase][o * SS + n] = make_int4(xr, hr, __float_as_int(mv), 0);
            n++;
        }
    }
    g_cnt[phase][o] = n;
}

// ---------------------------------------------------------------------------
// Kernel 4: G = [hidden@Wi^T+bi | hidden@Wh^T+bh], M=1537, N=1536, K=256.
// 64x128 tile, 4x8 micro via f32x2 pairs across j, BK=16, smem double buffer.
// ---------------------------------------------------------------------------
__global__ void __launch_bounds__(256) gates_gemm(
    int srcSel,
    const float* __restrict__ Wi, const float* __restrict__ Wh,
    const float* __restrict__ bi, const float* __restrict__ bh)
{
    __shared__ __align__(16) float As[2][16][68];
    __shared__ __align__(16) float Bs[2][16][132];
    const float* __restrict__ A = srcSel ? g_hidB : g_hidA;
    const int mb = blockIdx.x * 64;
    const int nb = blockIdx.y * 128;
    const int tid = threadIdx.x;
    const int tx = tid & 15, ty = tid >> 4;
    const bool half = (nb >= G3);
    const float* __restrict__ W = half ? Wh : Wi;
    const float* __restrict__ bias = half ? bh : bi;
    const int nw = half ? nb - G3 : nb;

    const int am = tid >> 2, akq = (tid & 3) * 4;
    const bool av_ok = (mb + am) < NHID;
    const int f0 = tid * 2, bm0 = f0 >> 2, bkq0 = (f0 & 3) * 4;
    const int f1 = tid * 2 + 1, bm1 = f1 >> 2, bkq1 = (f1 & 3) * 4;

    u64 accp[4][4];
    {
        float4 bv0 = *(const float4*)&bias[nw + tx * 4];
        float4 bv1 = *(const float4*)&bias[nw + 64 + tx * 4];
        u64 p0 = packf2(bv0.x, bv0.y), p1 = packf2(bv0.z, bv0.w);
        u64 p2 = packf2(bv1.x, bv1.y), p3 = packf2(bv1.z, bv1.w);
#pragma unroll
        for (int i = 0; i < 4; i++) {
            accp[i][0] = p0; accp[i][1] = p1; accp[i][2] = p2; accp[i][3] = p3;
        }
    }

    const float4 Z = make_float4(0.f, 0.f, 0.f, 0.f);
    float4 ra, rb0, rb1;
    ra  = av_ok ? *(const float4*)&A[(size_t)(mb + am) * D2 + akq] : Z;
    rb0 = *(const float4*)&W[(size_t)(nw + bm0) * D2 + bkq0];
    rb1 = *(const float4*)&W[(size_t)(nw + bm1) * D2 + bkq1];
    As[0][akq + 0][am] = ra.x; As[0][akq + 1][am] = ra.y; As[0][akq + 2][am] = ra.z; As[0][akq + 3][am] = ra.w;
    Bs[0][bkq0 + 0][bm0] = rb0.x; Bs[0][bkq0 + 1][bm0] = rb0.y; Bs[0][bkq0 + 2][bm0] = rb0.z; Bs[0][bkq0 + 3][bm0] = rb0.w;
    Bs[0][bkq1 + 0][bm1] = rb1.x; Bs[0][bkq1 + 1][bm1] = rb1.y; Bs[0][bkq1 + 2][bm1] = rb1.z; Bs[0][bkq1 + 3][bm1] = rb1.w;
    __syncthreads();

    for (int c = 0; c < 16; c++) {
        const int cur = c & 1;
        if (c < 15) {
            int k0 = (c + 1) * 16;
            ra  = av_ok ? *(const float4*)&A[(size_t)(mb + am) * D2 + k0 + akq] : Z;
            rb0 = *(const float4*)&W[(size_t)(nw + bm0) * D2 + k0 + bkq0];
            rb1 = *(const float4*)&W[(size_t)(nw + bm1) * D2 + k0 + bkq1];
        }
#pragma unroll
        for (int kk = 0; kk < 16; kk++) {
            float4 a0 = *(const float4*)&As[cur][kk][ty * 4];
            ulonglong2 bp0 = *(const ulonglong2*)&Bs[cur][kk][tx * 4];
            ulonglong2 bp1 = *(const ulonglong2*)&Bs[cur][kk][64 + tx * 4];
            float av[4] = {a0.x, a0.y, a0.z, a0.w};
#pragma unroll
            for (int i = 0; i < 4; i++) {
                u64 ad = packf2(av[i], av[i]);
                fma2(accp[i][0], ad, bp0.x);
                fma2(accp[i][1], ad, bp0.y);
                fma2(accp[i][2], ad, bp1.x);
                fma2(accp[i][3], ad, bp1.y);
            }
        }
        if (c < 15) {
            const int nxt = 1 - cur;
            As[nxt][akq + 0][am] = ra.x; As[nxt][akq + 1][am] = ra.y; As[nxt][akq + 2][am] = ra.z; As[nxt][akq + 3][am] = ra.w;
            Bs[nxt][bkq0 + 0][bm0] = rb0.x; Bs[nxt][bkq0 + 1][bm0] = rb0.y; Bs[nxt][bkq0 + 2][bm0] = rb0.z; Bs[nxt][bkq0 + 3][bm0] = rb0.w;
            Bs[nxt][bkq1 + 0][bm1] = rb1.x; Bs[nxt][bkq1 + 1][bm1] = rb1.y; Bs[nxt][bkq1 + 2][bm1] = rb1.z; Bs[nxt][bkq1 + 3][bm1] = rb1.w;
            __syncthreads();
        }
    }
#pragma unroll
    for (int i = 0; i < 4; i++) {
        int m = mb + ty * 4 + i;
        if (m < NHID) {
            size_t base = (size_t)m * GW + nb;
            float2 q0 = unpackf2(accp[i][0]), q1 = unpackf2(accp[i][1]);
            float2 q2 = unpackf2(accp[i][2]), q3 = unpackf2(accp[i][3]);
            float4 o0 = {q0.x, q0.y, q1.x, q1.y};
            float4 o1 = {q2.x, q2.y, q3.x, q3.y};
            *(float4*)&g_G[base + tx * 4] = o0;
            *(float4*)&g_G[base + 64 + tx * 4] = o1;
        }
    }
}

// ---------------------------------------------------------------------------
// Kernel 5: GRU + masked sum + norm-scaled residual update (table-driven).
// ---------------------------------------------------------------------------
__global__ void __launch_bounds__(256) gru_kernel(
    int srcSel, int dstSel, float* __restrict__ extDst, int phase)
{
    const float* __restrict__ hid = srcSel ? g_hidB : g_hidA;
    float* __restrict__ dst = (dstSel == 2) ? extDst : (dstSel ? g_hidB : g_hidA);
    const int o = blockIdx.x;
    const int d = threadIdx.x;
    if (o == 0) dst[d] = hid[d];

    const int n = g_cnt[phase][o];
    const int4* __restrict__ tab = g_tab[phase] + o * SS;

    float acc = 0.f;
#pragma unroll 2
    for (int e = 0; e < n; e++) {
        int4 t = __ldg(&tab[e]);
        const float* __restrict__ gi = g_G + (size_t)t.x * GW;
        const float* __restrict__ gh = g_G + (size_t)t.y * GW + G3;
        float r = sigf(gi[d] + gh[d]);
        float z = sigf(gi[256 + d] + gh[256 + d]);
        float nn = tanhfast(gi[512 + d] + r * gh[512 + d]);
        float hv = hid[t.y * D2 + d];
        acc += __int_as_float(t.z) * ((1.f - z) * nn + z * hv);
    }
    __shared__ float sm[256];
    sm[d] = acc * acc;
    __syncthreads();
    for (int s = 128; s > 0; s >>= 1) {
        if (d < s) sm[d] += sm[d + s];
        __syncthreads();
    }
    float v = sqrtf(sm[0]);
    float scale = (v + 0.25f) / (v + 1.f);
    dst[(o + 1) * D2 + d] = hid[(o + 1) * D2 + d] + acc * scale;
}

// ---------------------------------------------------------------------------
extern "C" void kernel_launch(void* const* d_in, const int* in_sizes, int n_in,
                              void* d_out, int out_size)
{
    const int*   enc    = (const int*)  d_in[0];
    const int*   sp     = (const int*)  d_in[1];
    const int*   sc     = (const int*)  d_in[2];
    const float* mask   = (const float*)d_in[3];
    const float* emb    = (const float*)d_in[4];
    const float* Wih_f  = (const float*)d_in[5];
    const float* Whh_f  = (const float*)d_in[6];
    const float* b_f    = (const float*)d_in[7];
    const float* Wih_b  = (const float*)d_in[8];
    const float* Whh_b  = (const float*)d_in[9];
    const float* b_b    = (const float*)d_in[10];
    const float* Wc     = (const float*)d_in[11];
    const float* bc     = (const float*)d_in[12];
    const float* Whr    = (const float*)d_in[13];
    const float* bhr    = (const float*)d_in[14];
    const float* Wi_cp  = (const float*)d_in[15];
    const float* Wh_cp  = (const float*)d_in[16];
    const float* bi_cp  = (const float*)d_in[17];
    const float* bh_cp  = (const float*)d_in[18];
    const float* Wi_pc  = (const float*)d_in[19];
    const float* Wh_pc  = (const float*)d_in[20];
    const float* bi_pc  = (const float*)d_in[21];
    const float* bh_pc  = (const float*)d_in[22];
    float* out = (float*)d_out;
    (void)in_sizes; (void)n_in; (void)out_size;

    // 0) structural tables + packed recurrent weights
    build_tables<<<(2 * NR + 255) / 256, 256>>>(sp, sc, mask);
    pack_whh<<<(512 * 128 + 255) / 256, 256>>>(Whh_f, Whh_b);

    // 1) vocab-side x-gates, single launch (z = dir) -> lstm is launch #4
    evoc_kernel<<<dim3(VSZ / 128, G4 / 128, 2), 256>>>(emb, Wih_f, b_f, Wih_b, b_b);

    // 2) recurrent LSTM: 440 blocks = 2.97/SM single wave, 6 warps/SMSP
    lstm_kernel<<<dim3(LBLOCKS, 2), LTHREADS>>>(enc);

    // 3) build hidden (g_hidA)
    reduce_kernel<<<NR / 8, 256>>>(Wc, bc, Whr, bhr);

    // 4) 2x cp + 2x pc GRU structure updates, ping-pong A->B->A->B->out
    for (int it = 0; it < 4; it++) {
        int phase  = it >> 1;
        int srcSel = it & 1;
        int dstSel = (it == 3) ? 2 : (1 - (it & 1));
        const float* Wi = phase ? Wi_pc : Wi_cp;
        const float* Wh = phase ? Wh_pc : Wh_cp;
        const float* bi = phase ? bi_pc : bi_cp;
        const float* bh = phase ? bh_pc : bh_cp;
        gates_gemm<<<dim3((NHID + 63) / 64, GW / 128), 256>>>(srcSel, Wi, Wh, bi, bh);
        gru_kernel<<<NR, 256>>>(srcSel, dstSel, out, phase);
    }
}

// round 11
// speedup vs baseline: 1.0411x; 1.0411x over previous
#include <cuda_runtime.h>
#include <math.h>

#define BB 16
#define SS 96
#define TT 50
#define NR 1536          // B*S
#define NHID 1537        // rows of "hidden"
#define HID 128
#define G4 512           // 4*H
#define D2 256
#define G3 768           // 3*D2
#define GW 1536          // Gi(768) | Gh(768)
#define VSZ 32000

#define LROWS 11
#define LTHREADS 256
#define LBLOCKS 140      // ceil(1536/11)

typedef unsigned long long u64;

// ---------------- scratch (device globals; no allocations) ----------------
__device__ float g_Evoc[2][(size_t)VSZ * G4];  // emb_table @ Wih^T + b, per dir
__device__ float g_Wtp[2][128 * 512];          // packed: [k/4][j][k%4]
__device__ float g_hT[2][NR * HID];
__device__ float g_cT[2][NR * HID];
__device__ float g_hidA[NHID * D2];
__device__ float g_hidB[NHID * D2];
__device__ float g_G[NHID * GW];               // [Gi | Gh] per row
__device__ int   g_cnt[2][NR];
__device__ int4  g_tab[2][NR * SS];

__device__ __forceinline__ float sigf(float x) { return 1.f / (1.f + __expf(-x)); }
__device__ __forceinline__ float tanhfast(float x) {
    float t = __expf(2.f * x);
    return 1.f - 2.f / (t + 1.f);
}

// ---- packed f32x2 helpers (Blackwell sm_103a) ----
__device__ __forceinline__ void fma2(u64& d, u64 a, u64 b) {
    asm("fma.rn.f32x2 %0, %1, %2, %0;" : "+l"(d) : "l"(a), "l"(b));
}
__device__ __forceinline__ u64 packf2(float lo, float hi) {
    u64 r; asm("mov.b64 %0, {%1, %2};" : "=l"(r) : "f"(lo), "f"(hi)); return r;
}
__device__ __forceinline__ float2 unpackf2(u64 v) {
    float2 r; asm("mov.b64 {%0, %1}, %2;" : "=f"(r.x), "=f"(r.y) : "l"(v)); return r;
}

// ---------------------------------------------------------------------------
// Kernel 0b: pack Whh as Wtp[(k>>2)*2048 + j*4 + (k%4)] -> thread j fetches its
// 4-k quad with one coalesced LDG.128; quad = two natural f32x2 k-pairs.
// ---------------------------------------------------------------------------
__global__ void __launch_bounds__(256) pack_whh(
    const float* __restrict__ Whh_f, const float* __restrict__ Whh_b)
{
    int idx = blockIdx.x * blockDim.x + threadIdx.x;
    if (idx >= 512 * 128) return;
    int j = idx >> 7, k = idx & 127;
    int dst = (k >> 2) * 2048 + j * 4 + (k & 3);
    g_Wtp[0][dst] = Whh_f[idx];
    g_Wtp[1][dst] = Whh_b[idx];
}

// ---------------------------------------------------------------------------
// Kernel 1: Evoc[dir] = emb_table @ W^T + b.  M=32000, N=512, K=128.
// 128x128 tile, 8x8 micro via f32x2 pairs across j, BK=16, smem double buffer.
// ---------------------------------------------------------------------------
__global__ void __launch_bounds__(256) evoc_kernel(
    const float* __restrict__ emb,
    const float* __restrict__ Wf, const float* __restrict__ bf,
    const float* __restrict__ Wb, const float* __restrict__ bb)
{
    __shared__ __align__(16) float As[2][16][132];
    __shared__ __align__(16) float Bs[2][16][132];

    const int dir = blockIdx.z;
    const float* __restrict__ W = dir ? Wb : Wf;
    const float* __restrict__ bias = dir ? bb : bf;
    float* __restrict__ C = g_Evoc[dir];

    const int mb = blockIdx.x * 128;
    const int nb = blockIdx.y * 128;
    const int tid = threadIdx.x;
    const int tx = tid & 15, ty = tid >> 4;

    const int f0 = tid * 2, m0 = f0 >> 2, kq0 = (f0 & 3) * 4;
    const int f1 = tid * 2 + 1, m1 = f1 >> 2, kq1 = (f1 & 3) * 4;

    u64 accp[8][4];
    {
        float4 bv0 = *(const float4*)&bias[nb + tx * 4];
        float4 bv1 = *(const float4*)&bias[nb + 64 + tx * 4];
        u64 p0 = packf2(bv0.x, bv0.y), p1 = packf2(bv0.z, bv0.w);
        u64 p2 = packf2(bv1.x, bv1.y), p3 = packf2(bv1.z, bv1.w);
#pragma unroll
        for (int i = 0; i < 8; i++) {
            accp[i][0] = p0; accp[i][1] = p1; accp[i][2] = p2; accp[i][3] = p3;
        }
    }

    float4 ra0, ra1, rb0, rb1;
    ra0 = *(const float4*)&emb[(size_t)(mb + m0) * 128 + kq0];
    ra1 = *(const float4*)&emb[(size_t)(mb + m1) * 128 + kq1];
    rb0 = *(const float4*)&W[(size_t)(nb + m0) * 128 + kq0];
    rb1 = *(const float4*)&W[(size_t)(nb + m1) * 128 + kq1];
    As[0][kq0 + 0][m0] = ra0.x; As[0][kq0 + 1][m0] = ra0.y; As[0][kq0 + 2][m0] = ra0.z; As[0][kq0 + 3][m0] = ra0.w;
    As[0][kq1 + 0][m1] = ra1.x; As[0][kq1 + 1][m1] = ra1.y; As[0][kq1 + 2][m1] = ra1.z; As[0][kq1 + 3][m1] = ra1.w;
    Bs[0][kq0 + 0][m0] = rb0.x; Bs[0][kq0 + 1][m0] = rb0.y; Bs[0][kq0 + 2][m0] = rb0.z; Bs[0][kq0 + 3][m0] = rb0.w;
    Bs[0][kq1 + 0][m1] = rb1.x; Bs[0][kq1 + 1][m1] = rb1.y; Bs[0][kq1 + 2][m1] = rb1.z; Bs[0][kq1 + 3][m1] = rb1.w;
    __syncthreads();

    for (int c = 0; c < 8; c++) {
        const int cur = c & 1;
        if (c < 7) {
            int k0 = (c + 1) * 16;
            ra0 = *(const float4*)&emb[(size_t)(mb + m0) * 128 + k0 + kq0];
            ra1 = *(const float4*)&emb[(size_t)(mb + m1) * 128 + k0 + kq1];
            rb0 = *(const float4*)&W[(size_t)(nb + m0) * 128 + k0 + kq0];
            rb1 = *(const float4*)&W[(size_t)(nb + m1) * 128 + k0 + kq1];
        }
#pragma unroll
        for (int kk = 0; kk < 16; kk++) {
            float4 a0 = *(const float4*)&As[cur][kk][ty * 4];
            float4 a1 = *(const float4*)&As[cur][kk][64 + ty * 4];
            ulonglong2 bp0 = *(const ulonglong2*)&Bs[cur][kk][tx * 4];
            ulonglong2 bp1 = *(const ulonglong2*)&Bs[cur][kk][64 + tx * 4];
            float av[8] = {a0.x,a0.y,a0.z,a0.w,a1.x,a1.y,a1.z,a1.w};
#pragma unroll
            for (int i = 0; i < 8; i++) {
                u64 ad = packf2(av[i], av[i]);
                fma2(accp[i][0], ad, bp0.x);
                fma2(accp[i][1], ad, bp0.y);
                fma2(accp[i][2], ad, bp1.x);
                fma2(accp[i][3], ad, bp1.y);
            }
        }
        if (c < 7) {
            const int nxt = 1 - cur;
            As[nxt][kq0 + 0][m0] = ra0.x; As[nxt][kq0 + 1][m0] = ra0.y; As[nxt][kq0 + 2][m0] = ra0.z; As[nxt][kq0 + 3][m0] = ra0.w;
            As[nxt][kq1 + 0][m1] = ra1.x; As[nxt][kq1 + 1][m1] = ra1.y; As[nxt][kq1 + 2][m1] = ra1.z; As[nxt][kq1 + 3][m1] = ra1.w;
            Bs[nxt][kq0 + 0][m0] = rb0.x; Bs[nxt][kq0 + 1][m0] = rb0.y; Bs[nxt][kq0 + 2][m0] = rb0.z; Bs[nxt][kq0 + 3][m0] = rb0.w;
            Bs[nxt][kq1 + 0][m1] = rb1.x; Bs[nxt][kq1 + 1][m1] = rb1.y; Bs[nxt][kq1 + 2][m1] = rb1.z; Bs[nxt][kq1 + 3][m1] = rb1.w;
            __syncthreads();
        }
    }
#pragma unroll
    for (int i = 0; i < 8; i++) {
        int row = mb + (i < 4 ? ty * 4 + i : 64 + ty * 4 + (i - 4));
        size_t base = (size_t)row * G4 + nb;
        float2 q0 = unpackf2(accp[i][0]), q1 = unpackf2(accp[i][1]);
        float2 q2 = unpackf2(accp[i][2]), q3 = unpackf2(accp[i][3]);
        float4 o0 = {q0.x, q0.y, q1.x, q1.y};
        float4 o1 = {q2.x, q2.y, q3.x, q3.y};
        *(float4*)&C[base + tx * 4] = o0;
        *(float4*)&C[base + 64 + tx * 4] = o1;
    }
}

// ---------------------------------------------------------------------------
// Kernel 2: LSTM recurrence, f32x2 paired accumulators, occ 2, with an
// EXPLICIT register double-buffer on the weight stream: chunk q+1's two
// LDG.128 quads are issued before chunk q's 44 FFMA2 (unroll 4 keeps ~4
// loads in flight), hiding the 234-262cyc L2 latency that R9/R10 exposed.
// ~107 regs -> no spill at the 128-reg occupancy-2 budget.
// ---------------------------------------------------------------------------
__global__ void __launch_bounds__(LTHREADS, 2) lstm_kernel(const int* __restrict__ enc)
{
    const int dir = blockIdx.y;
    const int rowBase = blockIdx.x * LROWS;
    const float* __restrict__ Wp = g_Wtp[dir];
    const float* __restrict__ Ev = g_Evoc[dir];
    const int tid = threadIdx.x;
    const int j0 = tid, j1 = tid + 256;

    __shared__ __align__(16) float hs[LROWS][128];
    __shared__ __align__(16) float cs[LROWS][128];
    __shared__ float gs[LROWS][512];
    __shared__ int toks[LROWS * TT];

    for (int e = tid; e < LROWS * 128; e += LTHREADS) {
        ((float*)hs)[e] = 0.f; ((float*)cs)[e] = 0.f;
    }
    for (int x = tid; x < LROWS * TT; x += LTHREADS) {
        int r = x / TT, tt = x % TT;
        int row = rowBase + r; if (row > NR - 1) row = NR - 1;   // clamp pad rows
        toks[x] = enc[row * TT + tt];
    }
    __syncthreads();

    // prefetch step-0 x-gates into registers
    float xa0[LROWS], xa1[LROWS];
    {
        const int te0 = dir ? (TT - 1) : 0;
#pragma unroll
        for (int r = 0; r < LROWS; r++) {
            const float* ev = Ev + (size_t)toks[r * TT + te0] * G4;
            xa0[r] = __ldg(&ev[j0]);
            xa1[r] = __ldg(&ev[j1]);
        }
    }

#pragma unroll 1
    for (int t = 0; t < TT; t++) {
        u64 accA[LROWS], accB[LROWS];
#pragma unroll
        for (int r = 0; r < LROWS; r++) {
            accA[r] = packf2(xa0[r], 0.f);
            accB[r] = packf2(xa1[r], 0.f);
        }

        if (t + 1 < TT) {      // prefetch next step's gather behind this step's FMA
            const int tn = dir ? (TT - 2 - t) : (t + 1);
#pragma unroll
            for (int r = 0; r < LROWS; r++) {
                const float* ev = Ev + (size_t)toks[r * TT + tn] * G4;
                xa0[r] = __ldg(&ev[j0]);
                xa1[r] = __ldg(&ev[j1]);
            }
        }

        // h @ Whh^T with explicit weight pipeline: issue chunk q+1 loads,
        // then compute chunk q. 2 LDG.128 + 11 LDS.128 + 44 FFMA2 per chunk.
        {
            ulonglong2 wA = __ldg((const ulonglong2*)&Wp[j0 * 4]);
            ulonglong2 wB = __ldg((const ulonglong2*)&Wp[j1 * 4]);
#pragma unroll 4
            for (int q = 0; q < 32; q++) {
                ulonglong2 wAn = wA, wBn = wB;
                if (q < 31) {
                    wAn = __ldg((const ulonglong2*)&Wp[(q + 1) * 2048 + j0 * 4]);
                    wBn = __ldg((const ulonglong2*)&Wp[(q + 1) * 2048 + j1 * 4]);
                }
#pragma unroll
                for (int r = 0; r < LROWS; r++) {
                    ulonglong2 h2 = *(const ulonglong2*)&hs[r][q * 4];
                    fma2(accA[r], wA.x, h2.x);
                    fma2(accA[r], wA.y, h2.y);
                    fma2(accB[r], wB.x, h2.x);
                    fma2(accB[r], wB.y, h2.y);
                }
                wA = wAn; wB = wBn;
            }
        }

#pragma unroll
        for (int r = 0; r < LROWS; r++) {
            float2 pA = unpackf2(accA[r]);
            float2 pB = unpackf2(accB[r]);
            gs[r][j0] = pA.x + pA.y;
            gs[r][j1] = pB.x + pB.y;
        }
        __syncthreads();
        for (int e = tid; e < LROWS * 128; e += LTHREADS) {
            int r = e >> 7, ch = e & 127;
            float gi = gs[r][ch],       gf = gs[r][128 + ch];
            float gg = gs[r][256 + ch], go = gs[r][384 + ch];
            float c = sigf(gf) * cs[r][ch] + sigf(gi) * tanhfast(gg);
            float h = sigf(go) * tanhfast(c);
            cs[r][ch] = c; hs[r][ch] = h;
        }
        __syncthreads();
    }

    for (int e = tid; e < LROWS * 128; e += LTHREADS) {
        int r = e >> 7, ch = e & 127;
        int n = rowBase + r;
        if (n < NR) {
            g_hT[dir][n * HID + ch] = hs[r][ch];
            g_cT[dir][n * HID + ch] = cs[r][ch];
        }
    }
}

// ---------------------------------------------------------------------------
// Kernel 3: hidden rows 1..1536 = [relu([cf|cb]@Wc^T+bc) | relu([hf|hb]@Whr^T+bhr)]
// ---------------------------------------------------------------------------
__global__ void __launch_bounds__(256) reduce_kernel(
    const float* __restrict__ Wc, const float* __restrict__ bc,
    const float* __restrict__ Whr, const float* __restrict__ bhr)
{
    const int nb = blockIdx.x * 8;
    const int tid = threadIdx.x;
    __shared__ __align__(16) float inA[8][256];
    __shared__ __align__(16) float inB[8][256];
    for (int x = tid; x < 8 * 256; x += 256) {
        int r = x >> 8, k = x & 255;
        int n = nb + r;
        inA[r][k] = (k < 128) ? g_cT[0][n * HID + k] : g_cT[1][n * HID + (k - 128)];
        inB[r][k] = (k < 128) ? g_hT[0][n * HID + k] : g_hT[1][n * HID + (k - 128)];
    }
    __syncthreads();

    const bool isC = tid < 128;
    const float* __restrict__ Wrow = isC ? (Wc + tid * 256) : (Whr + (tid - 128) * 256);
    const float bias = isC ? __ldg(&bc[tid]) : __ldg(&bhr[tid - 128]);
    const float (*IN)[256] = isC ? inA : inB;

    u64 accp[8];
#pragma unroll
    for (int r = 0; r < 8; r++) accp[r] = packf2(bias, 0.f);
#pragma unroll 4
    for (int k = 0; k < 256; k += 16) {
        ulonglong2 w0 = *(const ulonglong2*)&Wrow[k];
        ulonglong2 w1 = *(const ulonglong2*)&Wrow[k + 4];
        ulonglong2 w2 = *(const ulonglong2*)&Wrow[k + 8];
        ulonglong2 w3 = *(const ulonglong2*)&Wrow[k + 12];
#pragma unroll
        for (int r = 0; r < 8; r++) {
            ulonglong2 i0 = *(const ulonglong2*)&IN[r][k];
            ulonglong2 i1 = *(const ulonglong2*)&IN[r][k + 4];
            ulonglong2 i2 = *(const ulonglong2*)&IN[r][k + 8];
            ulonglong2 i3 = *(const ulonglong2*)&IN[r][k + 12];
            fma2(accp[r], w0.x, i0.x); fma2(accp[r], w0.y, i0.y);
            fma2(accp[r], w1.x, i1.x); fma2(accp[r], w1.y, i1.y);
            fma2(accp[r], w2.x, i2.x); fma2(accp[r], w2.y, i2.y);
            fma2(accp[r], w3.x, i3.x); fma2(accp[r], w3.y, i3.y);
        }
    }
#pragma unroll
    for (int r = 0; r < 8; r++) {
        float2 p = unpackf2(accp[r]);
        g_hidA[(nb + r + 1) * D2 + tid] = fmaxf(p.x + p.y, 0.f);
    }
    if (blockIdx.x == 0) g_hidA[tid] = 0.f;
}

// ---------------------------------------------------------------------------
// Kernel 3b: compacted active lists per (phase, output row). Deterministic.
// ---------------------------------------------------------------------------
__global__ void __launch_bounds__(256) build_tables(
    const int* __restrict__ sp, const int* __restrict__ sc,
    const float* __restrict__ mask)
{
    int g = blockIdx.x * blockDim.x + threadIdx.x;
    if (g >= 2 * NR) return;
    int phase = g >= NR;
    int o = g - phase * NR;
    int b = o / SS, q = o % SS;
    int n = 0;
    for (int u = 0; u < SS; u++) {
        int idx = phase ? ((b * SS + q) * SS + u) : ((b * SS + u) * SS + q);
        float mv = __ldg(&mask[idx]);
        if (mv != 0.f) {
            int par = __ldg(&sp[idx]);
            int chi = __ldg(&sc[idx]);
            int xr = phase ? par : chi;
            int hr = phase ? chi : par;
            g_tab[phase][o * SS + n] = make_int4(xr, hr, __float_as_int(mv), 0);
            n++;
        }
    }
    g_cnt[phase][o] = n;
}

// ---------------------------------------------------------------------------
// Kernel 4: G = [hidden@Wi^T+bi | hidden@Wh^T+bh], M=1537, N=1536, K=256.
// 64x128 tile, 4x8 micro via f32x2 pairs across j, BK=16, smem double buffer.
// ---------------------------------------------------------------------------
__global__ void __launch_bounds__(256) gates_gemm(
    int srcSel,
    const float* __restrict__ Wi, const float* __restrict__ Wh,
    const float* __restrict__ bi, const float* __restrict__ bh)
{
    __shared__ __align__(16) float As[2][16][68];
    __shared__ __align__(16) float Bs[2][16][132];
    const float* __restrict__ A = srcSel ? g_hidB : g_hidA;
    const int mb = blockIdx.x * 64;
    const int nb = blockIdx.y * 128;
    const int tid = threadIdx.x;
    const int tx = tid & 15, ty = tid >> 4;
    const bool half = (nb >= G3);
    const float* __restrict__ W = half ? Wh : Wi;
    const float* __restrict__ bias = half ? bh : bi;
    const int nw = half ? nb - G3 : nb;

    const int am = tid >> 2, akq = (tid & 3) * 4;
    const bool av_ok = (mb + am) < NHID;
    const int f0 = tid * 2, bm0 = f0 >> 2, bkq0 = (f0 & 3) * 4;
    const int f1 = tid * 2 + 1, bm1 = f1 >> 2, bkq1 = (f1 & 3) * 4;

    u64 accp[4][4];
    {
        float4 bv0 = *(const float4*)&bias[nw + tx * 4];
        float4 bv1 = *(const float4*)&bias[nw + 64 + tx * 4];
        u64 p0 = packf2(bv0.x, bv0.y), p1 = packf2(bv0.z, bv0.w);
        u64 p2 = packf2(bv1.x, bv1.y), p3 = packf2(bv1.z, bv1.w);
#pragma unroll
        for (int i = 0; i < 4; i++) {
            accp[i][0] = p0; accp[i][1] = p1; accp[i][2] = p2; accp[i][3] = p3;
        }
    }

    const float4 Z = make_float4(0.f, 0.f, 0.f, 0.f);
    float4 ra, rb0, rb1;
    ra  = av_ok ? *(const float4*)&A[(size_t)(mb + am) * D2 + akq] : Z;
    rb0 = *(const float4*)&W[(size_t)(nw + bm0) * D2 + bkq0];
    rb1 = *(const float4*)&W[(size_t)(nw + bm1) * D2 + bkq1];
    As[0][akq + 0][am] = ra.x; As[0][akq + 1][am] = ra.y; As[0][akq + 2][am] = ra.z; As[0][akq + 3][am] = ra.w;
    Bs[0][bkq0 + 0][bm0] = rb0.x; Bs[0][bkq0 + 1][bm0] = rb0.y; Bs[0][bkq0 + 2][bm0] = rb0.z; Bs[0][bkq0 + 3][bm0] = rb0.w;
    Bs[0][bkq1 + 0][bm1] = rb1.x; Bs[0][bkq1 + 1][bm1] = rb1.y; Bs[0][bkq1 + 2][bm1] = rb1.z; Bs[0][bkq1 + 3][bm1] = rb1.w;
    __syncthreads();

    for (int c = 0; c < 16; c++) {
        const int cur = c & 1;
        if (c < 15) {
            int k0 = (c + 1) * 16;
            ra  = av_ok ? *(const float4*)&A[(size_t)(mb + am) * D2 + k0 + akq] : Z;
            rb0 = *(const float4*)&W[(size_t)(nw + bm0) * D2 + k0 + bkq0];
            rb1 = *(const float4*)&W[(size_t)(nw + bm1) * D2 + k0 + bkq1];
        }
#pragma unroll
        for (int kk = 0; kk < 16; kk++) {
            float4 a0 = *(const float4*)&As[cur][kk][ty * 4];
            ulonglong2 bp0 = *(const ulonglong2*)&Bs[cur][kk][tx * 4];
            ulonglong2 bp1 = *(const ulonglong2*)&Bs[cur][kk][64 + tx * 4];
            float av[4] = {a0.x, a0.y, a0.z, a0.w};
#pragma unroll
            for (int i = 0; i < 4; i++) {
                u64 ad = packf2(av[i], av[i]);
                fma2(accp[i][0], ad, bp0.x);
                fma2(accp[i][1], ad, bp0.y);
                fma2(accp[i][2], ad, bp1.x);
                fma2(accp[i][3], ad, bp1.y);
            }
        }
        if (c < 15) {
            const int nxt = 1 - cur;
            As[nxt][akq + 0][am] = ra.x; As[nxt][akq + 1][am] = ra.y; As[nxt][akq + 2][am] = ra.z; As[nxt][akq + 3][am] = ra.w;
            Bs[nxt][bkq0 + 0][bm0] = rb0.x; Bs[nxt][bkq0 + 1][bm0] = rb0.y; Bs[nxt][bkq0 + 2][bm0] = rb0.z; Bs[nxt][bkq0 + 3][bm0] = rb0.w;
            Bs[nxt][bkq1 + 0][bm1] = rb1.x; Bs[nxt][bkq1 + 1][bm1] = rb1.y; Bs[nxt][bkq1 + 2][bm1] = rb1.z; Bs[nxt][bkq1 + 3][bm1] = rb1.w;
            __syncthreads();
        }
    }
#pragma unroll
    for (int i = 0; i < 4; i++) {
        int m = mb + ty * 4 + i;
        if (m < NHID) {
            size_t base = (size_t)m * GW + nb;
            float2 q0 = unpackf2(accp[i][0]), q1 = unpackf2(accp[i][1]);
            float2 q2 = unpackf2(accp[i][2]), q3 = unpackf2(accp[i][3]);
            float4 o0 = {q0.x, q0.y, q1.x, q1.y};
            float4 o1 = {q2.x, q2.y, q3.x, q3.y};
            *(float4*)&g_G[base + tx * 4] = o0;
            *(float4*)&g_G[base + 64 + tx * 4] = o1;
        }
    }
}

// ---------------------------------------------------------------------------
// Kernel 5: GRU + masked sum + norm-scaled residual update (table-driven).
// Reduction via shfl + 1 barrier (was 8-barrier smem tree).
// ---------------------------------------------------------------------------
__global__ void __launch_bounds__(256) gru_kernel(
    int srcSel, int dstSel, float* __restrict__ extDst, int phase)
{
    const float* __restrict__ hid = srcSel ? g_hidB : g_hidA;
    float* __restrict__ dst = (dstSel == 2) ? extDst : (dstSel ? g_hidB : g_hidA);
    const int o = blockIdx.x;
    const int d = threadIdx.x;
    if (o == 0) dst[d] = hid[d];

    const int n = g_cnt[phase][o];
    const int4* __restrict__ tab = g_tab[phase] + o * SS;

    float acc = 0.f;
#pragma unroll 2
    for (int e = 0; e < n; e++) {
        int4 t = __ldg(&tab[e]);
        const float* __restrict__ gi = g_G + (size_t)t.x * GW;
        const float* __restrict__ gh = g_G + (size_t)t.y * GW + G3;
        float r = sigf(gi[d] + gh[d]);
        float z = sigf(gi[256 + d] + gh[256 + d]);
        float nn = tanhfast(gi[512 + d] + r * gh[512 + d]);
        float hv = hid[t.y * D2 + d];
        acc += __int_as_float(t.z) * ((1.f - z) * nn + z * hv);
    }
    // block reduction of acc^2: warp shfl + one smem stage
    __shared__ float wsum[8];
    float s = acc * acc;
#pragma unroll
    for (int off = 16; off > 0; off >>= 1)
        s += __shfl_xor_sync(0xffffffffu, s, off);
    if ((d & 31) == 0) wsum[d >> 5] = s;
    __syncthreads();
    float tot = wsum[0] + wsum[1] + wsum[2] + wsum[3]
              + wsum[4] + wsum[5] + wsum[6] + wsum[7];
    float v = sqrtf(tot);
    float scale = (v + 0.25f) / (v + 1.f);
    dst[(o + 1) * D2 + d] = hid[(o + 1) * D2 + d] + acc * scale;
}

// ---------------------------------------------------------------------------
extern "C" void kernel_launch(void* const* d_in, const int* in_sizes, int n_in,
                              void* d_out, int out_size)
{
    const int*   enc    = (const int*)  d_in[0];
    const int*   sp     = (const int*)  d_in[1];
    const int*   sc     = (const int*)  d_in[2];
    const float* mask   = (const float*)d_in[3];
    const float* emb    = (const float*)d_in[4];
    const float* Wih_f  = (const float*)d_in[5];
    const float* Whh_f  = (const float*)d_in[6];
    const float* b_f    = (const float*)d_in[7];
    const float* Wih_b  = (const float*)d_in[8];
    const float* Whh_b  = (const float*)d_in[9];
    const float* b_b    = (const float*)d_in[10];
    const float* Wc     = (const float*)d_in[11];
    const float* bc     = (const float*)d_in[12];
    const float* Whr    = (const float*)d_in[13];
    const float* bhr    = (const float*)d_in[14];
    const float* Wi_cp  = (const float*)d_in[15];
    const float* Wh_cp  = (const float*)d_in[16];
    const float* bi_cp  = (const float*)d_in[17];
    const float* bh_cp  = (const float*)d_in[18];
    const float* Wi_pc  = (const float*)d_in[19];
    const float* Wh_pc  = (const float*)d_in[20];
    const float* bi_pc  = (const float*)d_in[21];
    const float* bh_pc  = (const float*)d_in[22];
    float* out = (float*)d_out;
    (void)in_sizes; (void)n_in; (void)out_size;

    // 0) structural tables + packed recurrent weights
    build_tables<<<(2 * NR + 255) / 256, 256>>>(sp, sc, mask);
    pack_whh<<<(512 * 128 + 255) / 256, 256>>>(Whh_f, Whh_b);

    // 1) vocab-side x-gates, single launch (z = dir) -> lstm is launch #4
    evoc_kernel<<<dim3(VSZ / 128, G4 / 128, 2), 256>>>(emb, Wih_f, b_f, Wih_b, b_b);

    // 2) recurrent LSTM: 280 blocks (2/SM), pipelined weight stream
    lstm_kernel<<<dim3(LBLOCKS, 2), LTHREADS>>>(enc);

    // 3) build hidden (g_hidA)
    reduce_kernel<<<NR / 8, 256>>>(Wc, bc, Whr, bhr);

    // 4) 2x cp + 2x pc GRU structure updates, ping-pong A->B->A->B->out
    for (int it = 0; it < 4; it++) {
        int phase  = it >> 1;
        int srcSel = it & 1;
        int dstSel = (it == 3) ? 2 : (1 - (it & 1));
        const float* Wi = phase ? Wi_pc : Wi_cp;
        const float* Wh = phase ? Wh_pc : Wh_cp;
        const float* bi = phase ? bi_pc : bi_cp;
        const float* bh = phase ? bh_pc : bh_cp;
        gates_gemm<<<dim3((NHID + 63) / 64, GW / 128), 256>>>(srcSel, Wi, Wh, bi, bh);
        gru_kernel<<<NR, 256>>>(srcSel, dstSel, out, phase);
    }
}